// round 13
// baseline (speedup 1.0000x reference)
#include <cuda_runtime.h>

#define T_ 512
#define K_ 8
#define D_ 8
#define NB 2

// ---------- packed f32x2 helpers ----------
typedef unsigned long long u64_t;

static __device__ __forceinline__ u64_t pk2(float lo, float hi) {
    u64_t r;
    asm("mov.b64 %0, {%1, %2};" : "=l"(r) : "f"(lo), "f"(hi));
    return r;
}
static __device__ __forceinline__ void upk2(u64_t v, float& lo, float& hi) {
    asm("mov.b64 {%0, %1}, %2;" : "=f"(lo), "=f"(hi) : "l"(v));
}
static __device__ __forceinline__ u64_t fma2_(u64_t a, u64_t b, u64_t c) {
    u64_t d;
    asm("fma.rn.f32x2 %0, %1, %2, %3;" : "=l"(d) : "l"(a), "l"(b), "l"(c));
    return d;
}
static __device__ __forceinline__ u64_t mul2_(u64_t a, u64_t b) {
    u64_t d;
    asm("mul.rn.f32x2 %0, %1, %2;" : "=l"(d) : "l"(a), "l"(b));
    return d;
}
static __device__ __forceinline__ float ex2_(float a) {
    float r;
    asm("ex2.approx.f32 %0, %1;" : "=f"(r) : "f"(a));
    return r;
}

// ============================================================================
// Single fused kernel. One block per (b-chunk, t); 128 threads; NB=2 outputs
// per thread (256 b per block).
//
// Param build (in-block, threads 0-63 = warps 0-1):
//   8 threads per (t,k): distributed pivot-free Gauss-Jordan of (I+A) via
//   width-8 shfl; Q = 2*inv(I+A) - I; columns scaled by
//   s_d = sqrt(0.5*exp(-clip(lv))*log2e); bias = -(center.Q)*s.
//   Thread 64 does the softmax of clipped weight logits in parallel.
//   Results go straight to shared memory (no second launch, no gmem staging).
//
// Main loop (round-12 body, NB=2):
//   p[b,t] = sum_k ex2( lw_k - sum_d z_d^2 ),  z = x . Qs + bs
//   packed fma.rn.f32x2 over j-pairs; x-dup packs are per-(b,i) and hoisted
//   over k by ptxas — do NOT restructure (round-3 post-mortem).
// ============================================================================
__global__ void __launch_bounds__(128, 6)
pecd_fused_kernel(const float* __restrict__ x,
                  const float* __restrict__ centers,
                  const float* __restrict__ wlog,
                  const float* __restrict__ logvar,
                  const float* __restrict__ cov,
                  float* __restrict__ out)
{
    const int t   = blockIdx.y;
    const int tid = threadIdx.x;

    __shared__ __align__(16) float sQ[K_ * 64];
    __shared__ __align__(16) float sB[K_ * 8];
    __shared__ float sLsum[K_];
    __shared__ float sW[K_];
    __shared__ float sLW[K_];

    // ---- issue x LDGs early (overlap with param build) ----
    const int b0 = blockIdx.x * (128 * NB) + tid;
    float xr[NB][8];
    {
        const float4* x4 = reinterpret_cast<const float4*>(x);
        #pragma unroll
        for (int ib = 0; ib < NB; ib++) {
            const int b = b0 + ib * 128;
            const float4 p0 = x4[(size_t)(b * T_ + t) * 2 + 0];
            const float4 p1 = x4[(size_t)(b * T_ + t) * 2 + 1];
            xr[ib][0] = p0.x; xr[ib][1] = p0.y; xr[ib][2] = p0.z; xr[ib][3] = p0.w;
            xr[ib][4] = p1.x; xr[ib][5] = p1.y; xr[ib][6] = p1.z; xr[ib][7] = p1.w;
        }
    }

    // ---- in-block param build ----
    if (tid < 64) {
        const int r  = tid & 7;        // GJ row owned by this thread
        const int k  = tid >> 3;       // kernel index
        const int tk = t * K_ + k;

        // build row r of M = I + A (A antisym from 28 cov params)
        // flat[j] = v[j] for j<28, v[55-j] for 28<=j<56
        const float* v = cov + tk * 28;
        float Mrow[8];
        #pragma unroll
        for (int c = 0; c < 8; c++) {
            float ut_rc = 0.f, ut_cr = 0.f;
            if (c > r) { int j = 8 * r + c; ut_rc = (j < 28) ? v[j] : v[55 - j]; }
            if (r > c) { int j = 8 * c + r; ut_cr = (j < 28) ? v[j] : v[55 - j]; }
            Mrow[c] = 0.5f * (ut_cr - ut_rc) + ((r == c) ? 1.f : 0.f);
        }

        // distributed pivot-free Gauss-Jordan inverse (stable: sym part of
        // I+A is positive definite)
        #pragma unroll
        for (int col = 0; col < 8; col++) {
            float prow[8];
            #pragma unroll
            for (int j = 0; j < 8; j++)
                prow[j] = __shfl_sync(0xffffffffu, Mrow[j], col, 8);
            const float p = 1.0f / prow[col];
            if (r == col) {
                #pragma unroll
                for (int j = 0; j < 8; j++)
                    Mrow[j] = (j == col) ? p : prow[j] * p;
            } else {
                const float f = Mrow[col];
                #pragma unroll
                for (int j = 0; j < 8; j++)
                    if (j != col) Mrow[j] = fmaf(-f, prow[j] * p, Mrow[j]);
                Mrow[col] = -f * p;
            }
        }

        // Q row = 2*inv(I+A) - I
        float Qrow[8];
        #pragma unroll
        for (int j = 0; j < 8; j++)
            Qrow[j] = 2.0f * Mrow[j] - ((r == j) ? 1.f : 0.f);

        // variance scale s_d (lane r owns d=r) and lsum
        const float LOG2PI = 1.8378770664093453f;
        const float LOG2E  = 1.4426950408889634f;
        float lv = logvar[tk * 8 + r];
        lv = fminf(fmaxf(lv, -3.5f), 3.5f);
        const float s_own = sqrtf(0.5f * expf(-lv) * LOG2E);
        {
            float lc = -0.5f * (LOG2PI + lv) * LOG2E;
            #pragma unroll
            for (int m = 1; m < 8; m <<= 1)
                lc += __shfl_xor_sync(0xffffffffu, lc, m, 8);
            if (r == 0) sLsum[k] = lc;
        }

        float s_all[8];
        #pragma unroll
        for (int j = 0; j < 8; j++)
            s_all[j] = __shfl_sync(0xffffffffu, s_own, j, 8);

        #pragma unroll
        for (int j = 0; j < 8; j++)
            sQ[k * 64 + r * 8 + j] = Qrow[j] * s_all[j];

        // bias_j = -(center.Q)_j, scaled by s_j; butterfly over lanes
        {
            const float cr = centers[tk * 8 + r];
            float s[8];
            #pragma unroll
            for (int j = 0; j < 8; j++) s[j] = cr * Qrow[j];
            #pragma unroll
            for (int m = 1; m < 8; m <<= 1) {
                #pragma unroll
                for (int j = 0; j < 8; j++)
                    s[j] += __shfl_xor_sync(0xffffffffu, s[j], m, 8);
            }
            sB[k * 8 + r] = -s[r] * s_own;
        }
    } else if (tid == 64) {
        // softmax of clipped weight logits for this t
        float l[K_];
        float mx = -1e30f;
        #pragma unroll
        for (int k = 0; k < K_; k++) {
            float v = wlog[t * K_ + k];
            v = fminf(fmaxf(v, -3.5f), 3.5f);
            l[k] = v;
            mx = fmaxf(mx, v);
        }
        float s = 0.f;
        #pragma unroll
        for (int k = 0; k < K_; k++) { l[k] = __expf(l[k] - mx); s += l[k]; }
        float inv = 1.0f / s;
        #pragma unroll
        for (int k = 0; k < K_; k++) sW[k] = l[k] * inv;
    }
    __syncthreads();
    if (tid < K_) sLW[tid] = sLsum[tid] + __log2f(sW[tid]);
    __syncthreads();

    // ---- main loop (round-12 body, NB=2) ----
    float acc[NB];
    #pragma unroll
    for (int ib = 0; ib < NB; ib++) acc[ib] = 0.f;

    #pragma unroll
    for (int k = 0; k < K_; k++) {
        const float4* q4 = reinterpret_cast<const float4*>(&sQ[k * 64]);

        const float4 bb0 = reinterpret_cast<const float4*>(&sB[k * 8])[0];
        const float4 bb1 = reinterpret_cast<const float4*>(&sB[k * 8])[1];
        u64_t bias01 = pk2(bb0.x, bb0.y), bias23 = pk2(bb0.z, bb0.w);
        u64_t bias45 = pk2(bb1.x, bb1.y), bias67 = pk2(bb1.z, bb1.w);

        u64_t xt[NB][4];
        #pragma unroll
        for (int ib = 0; ib < NB; ib++) {
            xt[ib][0] = bias01; xt[ib][1] = bias23;
            xt[ib][2] = bias45; xt[ib][3] = bias67;
        }

        // z_j += sum_i x_i * Qs[i][j]   (packed over j-pairs)
        #pragma unroll
        for (int i = 0; i < 8; i++) {
            const float4 qa = q4[2 * i + 0];
            const float4 qb = q4[2 * i + 1];
            const u64_t q01 = pk2(qa.x, qa.y), q23 = pk2(qa.z, qa.w);
            const u64_t q45 = pk2(qb.x, qb.y), q67 = pk2(qb.z, qb.w);
            #pragma unroll
            for (int ib = 0; ib < NB; ib++) {
                const u64_t xi = pk2(xr[ib][i], xr[ib][i]);
                xt[ib][0] = fma2_(xi, q01, xt[ib][0]);
                xt[ib][1] = fma2_(xi, q23, xt[ib][1]);
                xt[ib][2] = fma2_(xi, q45, xt[ib][2]);
                xt[ib][3] = fma2_(xi, q67, xt[ib][3]);
            }
        }

        const float lw = sLW[k];

        // exponent = lw - sum_d z_d^2 ; squares accumulate via fma2
        #pragma unroll
        for (int ib = 0; ib < NB; ib++) {
            u64_t a = mul2_(xt[ib][0], xt[ib][0]);
            a = fma2_(xt[ib][1], xt[ib][1], a);
            a = fma2_(xt[ib][2], xt[ib][2], a);
            a = fma2_(xt[ib][3], xt[ib][3], a);
            float lo, hi;
            upk2(a, lo, hi);
            acc[ib] += ex2_(lw - lo - hi);
        }
    }

    #pragma unroll
    for (int ib = 0; ib < NB; ib++) {
        const int b = b0 + ib * 128;
        out[(size_t)b * T_ + t] = acc[ib];
    }
}

// ============================================================================
extern "C" void kernel_launch(void* const* d_in, const int* in_sizes, int n_in,
                              void* d_out, int out_size)
{
    const float* x       = (const float*)d_in[0];  // [B, T, D]
    const float* centers = (const float*)d_in[1];  // [T, K, D]
    const float* wlog    = (const float*)d_in[2];  // [T, K]
    const float* logvar  = (const float*)d_in[3];  // [T, K, D]
    const float* cov     = (const float*)d_in[4];  // [T, K, 28]

    const int B = in_sizes[0] / (T_ * D_);         // 2048

    dim3 grid(B / (128 * NB), T_);                 // (8, 512)
    pecd_fused_kernel<<<grid, 128>>>(x, centers, wlog, logvar, cov, (float*)d_out);
}

// round 16
// speedup vs baseline: 1.1038x; 1.1038x over previous
#include <cuda_runtime.h>

#define T_ 512
#define K_ 8
#define D_ 8
#define NB 4

// ---------- packed f32x2 helpers ----------
typedef unsigned long long u64_t;

static __device__ __forceinline__ u64_t pk2(float lo, float hi) {
    u64_t r;
    asm("mov.b64 %0, {%1, %2};" : "=l"(r) : "f"(lo), "f"(hi));
    return r;
}
static __device__ __forceinline__ void upk2(u64_t v, float& lo, float& hi) {
    asm("mov.b64 {%0, %1}, %2;" : "=f"(lo), "=f"(hi) : "l"(v));
}
static __device__ __forceinline__ u64_t fma2_(u64_t a, u64_t b, u64_t c) {
    u64_t d;
    asm("fma.rn.f32x2 %0, %1, %2, %3;" : "=l"(d) : "l"(a), "l"(b), "l"(c));
    return d;
}
static __device__ __forceinline__ u64_t mul2_(u64_t a, u64_t b) {
    u64_t d;
    asm("mul.rn.f32x2 %0, %1, %2;" : "=l"(d) : "l"(a), "l"(b));
    return d;
}
static __device__ __forceinline__ float ex2_(float a) {
    float r;
    asm("ex2.approx.f32 %0, %1;" : "=f"(r) : "f"(a));
    return r;
}

// ============================================================================
// Single fused kernel. One block per (b-chunk, t); 128 threads; NB=4 outputs
// per thread (512 b per block; grid (4, 512)).
//
// Param build (in-block, threads 0-63 = warps 0-1, hidden under the x LDGs):
//   8 threads per (t,k): distributed pivot-free Gauss-Jordan of (I+A) via
//   width-8 shfl; Q = 2*inv(I+A) - I; columns scaled by
//   s_d = sqrt(0.5*exp(-clip(lv))*log2e); bias = -(center.Q)*s.
//   Thread 64 does the softmax of clipped weight logits in parallel.
//
// Main loop (round-12 body, NB=4 — L1-optimal amortization per round-13
// post-mortem; NB=2 makes LDS binding):
//   p[b,t] = sum_k ex2( lw_k - sum_d z_d^2 ),  z = x . Qs + bs
//   packed fma.rn.f32x2 over j-pairs; x-dup packs are per-(b,i) and hoisted
//   over k by ptxas — do NOT restructure (round-3 post-mortem).
// ============================================================================
__global__ void __launch_bounds__(128)
pecd_fused_kernel(const float* __restrict__ x,
                  const float* __restrict__ centers,
                  const float* __restrict__ wlog,
                  const float* __restrict__ logvar,
                  const float* __restrict__ cov,
                  float* __restrict__ out)
{
    const int t   = blockIdx.y;
    const int tid = threadIdx.x;

    __shared__ __align__(16) float sQ[K_ * 64];
    __shared__ __align__(16) float sB[K_ * 8];
    __shared__ float sLsum[K_];
    __shared__ float sW[K_];
    __shared__ float sLW[K_];

    // ---- issue x LDGs early (param build overlaps their latency) ----
    const int b0 = blockIdx.x * (128 * NB) + tid;
    float xr[NB][8];
    {
        const float4* x4 = reinterpret_cast<const float4*>(x);
        #pragma unroll
        for (int ib = 0; ib < NB; ib++) {
            const int b = b0 + ib * 128;
            const float4 p0 = x4[(size_t)(b * T_ + t) * 2 + 0];
            const float4 p1 = x4[(size_t)(b * T_ + t) * 2 + 1];
            xr[ib][0] = p0.x; xr[ib][1] = p0.y; xr[ib][2] = p0.z; xr[ib][3] = p0.w;
            xr[ib][4] = p1.x; xr[ib][5] = p1.y; xr[ib][6] = p1.z; xr[ib][7] = p1.w;
        }
    }

    // ---- in-block param build ----
    if (tid < 64) {
        const int r  = tid & 7;        // GJ row owned by this thread
        const int k  = tid >> 3;       // kernel index
        const int tk = t * K_ + k;

        // build row r of M = I + A (A antisym from 28 cov params)
        // flat[j] = v[j] for j<28, v[55-j] for 28<=j<56
        const float* v = cov + tk * 28;
        float Mrow[8];
        #pragma unroll
        for (int c = 0; c < 8; c++) {
            float ut_rc = 0.f, ut_cr = 0.f;
            if (c > r) { int j = 8 * r + c; ut_rc = (j < 28) ? v[j] : v[55 - j]; }
            if (r > c) { int j = 8 * c + r; ut_cr = (j < 28) ? v[j] : v[55 - j]; }
            Mrow[c] = 0.5f * (ut_cr - ut_rc) + ((r == c) ? 1.f : 0.f);
        }

        // distributed pivot-free Gauss-Jordan inverse (stable: sym part of
        // I+A is positive definite)
        #pragma unroll
        for (int col = 0; col < 8; col++) {
            float prow[8];
            #pragma unroll
            for (int j = 0; j < 8; j++)
                prow[j] = __shfl_sync(0xffffffffu, Mrow[j], col, 8);
            const float p = 1.0f / prow[col];
            if (r == col) {
                #pragma unroll
                for (int j = 0; j < 8; j++)
                    Mrow[j] = (j == col) ? p : prow[j] * p;
            } else {
                const float f = Mrow[col];
                #pragma unroll
                for (int j = 0; j < 8; j++)
                    if (j != col) Mrow[j] = fmaf(-f, prow[j] * p, Mrow[j]);
                Mrow[col] = -f * p;
            }
        }

        // Q row = 2*inv(I+A) - I
        float Qrow[8];
        #pragma unroll
        for (int j = 0; j < 8; j++)
            Qrow[j] = 2.0f * Mrow[j] - ((r == j) ? 1.f : 0.f);

        // variance scale s_d (lane r owns d=r) and lsum
        const float LOG2PI = 1.8378770664093453f;
        const float LOG2E  = 1.4426950408889634f;
        float lv = logvar[tk * 8 + r];
        lv = fminf(fmaxf(lv, -3.5f), 3.5f);
        const float s_own = sqrtf(0.5f * expf(-lv) * LOG2E);
        {
            float lc = -0.5f * (LOG2PI + lv) * LOG2E;
            #pragma unroll
            for (int m = 1; m < 8; m <<= 1)
                lc += __shfl_xor_sync(0xffffffffu, lc, m, 8);
            if (r == 0) sLsum[k] = lc;
        }

        float s_all[8];
        #pragma unroll
        for (int j = 0; j < 8; j++)
            s_all[j] = __shfl_sync(0xffffffffu, s_own, j, 8);

        #pragma unroll
        for (int j = 0; j < 8; j++)
            sQ[k * 64 + r * 8 + j] = Qrow[j] * s_all[j];

        // bias_j = -(center.Q)_j, scaled by s_j; butterfly over lanes
        {
            const float cr = centers[tk * 8 + r];
            float s[8];
            #pragma unroll
            for (int j = 0; j < 8; j++) s[j] = cr * Qrow[j];
            #pragma unroll
            for (int m = 1; m < 8; m <<= 1) {
                #pragma unroll
                for (int j = 0; j < 8; j++)
                    s[j] += __shfl_xor_sync(0xffffffffu, s[j], m, 8);
            }
            sB[k * 8 + r] = -s[r] * s_own;
        }
    } else if (tid == 64) {
        // softmax of clipped weight logits for this t
        float l[K_];
        float mx = -1e30f;
        #pragma unroll
        for (int k = 0; k < K_; k++) {
            float v = wlog[t * K_ + k];
            v = fminf(fmaxf(v, -3.5f), 3.5f);
            l[k] = v;
            mx = fmaxf(mx, v);
        }
        float s = 0.f;
        #pragma unroll
        for (int k = 0; k < K_; k++) { l[k] = __expf(l[k] - mx); s += l[k]; }
        float inv = 1.0f / s;
        #pragma unroll
        for (int k = 0; k < K_; k++) sW[k] = l[k] * inv;
    }
    __syncthreads();
    if (tid < K_) sLW[tid] = sLsum[tid] + __log2f(sW[tid]);
    __syncthreads();

    // ---- main loop (round-12 body, NB=4) ----
    float acc[NB];
    #pragma unroll
    for (int ib = 0; ib < NB; ib++) acc[ib] = 0.f;

    #pragma unroll
    for (int k = 0; k < K_; k++) {
        const float4* q4 = reinterpret_cast<const float4*>(&sQ[k * 64]);

        const float4 bb0 = reinterpret_cast<const float4*>(&sB[k * 8])[0];
        const float4 bb1 = reinterpret_cast<const float4*>(&sB[k * 8])[1];
        u64_t bias01 = pk2(bb0.x, bb0.y), bias23 = pk2(bb0.z, bb0.w);
        u64_t bias45 = pk2(bb1.x, bb1.y), bias67 = pk2(bb1.z, bb1.w);

        u64_t xt[NB][4];
        #pragma unroll
        for (int ib = 0; ib < NB; ib++) {
            xt[ib][0] = bias01; xt[ib][1] = bias23;
            xt[ib][2] = bias45; xt[ib][3] = bias67;
        }

        // z_j += sum_i x_i * Qs[i][j]   (packed over j-pairs)
        #pragma unroll
        for (int i = 0; i < 8; i++) {
            const float4 qa = q4[2 * i + 0];
            const float4 qb = q4[2 * i + 1];
            const u64_t q01 = pk2(qa.x, qa.y), q23 = pk2(qa.z, qa.w);
            const u64_t q45 = pk2(qb.x, qb.y), q67 = pk2(qb.z, qb.w);
            #pragma unroll
            for (int ib = 0; ib < NB; ib++) {
                const u64_t xi = pk2(xr[ib][i], xr[ib][i]);
                xt[ib][0] = fma2_(xi, q01, xt[ib][0]);
                xt[ib][1] = fma2_(xi, q23, xt[ib][1]);
                xt[ib][2] = fma2_(xi, q45, xt[ib][2]);
                xt[ib][3] = fma2_(xi, q67, xt[ib][3]);
            }
        }

        const float lw = sLW[k];

        // exponent = lw - sum_d z_d^2 ; squares accumulate via fma2
        #pragma unroll
        for (int ib = 0; ib < NB; ib++) {
            u64_t a = mul2_(xt[ib][0], xt[ib][0]);
            a = fma2_(xt[ib][1], xt[ib][1], a);
            a = fma2_(xt[ib][2], xt[ib][2], a);
            a = fma2_(xt[ib][3], xt[ib][3], a);
            float lo, hi;
            upk2(a, lo, hi);
            acc[ib] += ex2_(lw - lo - hi);
        }
    }

    #pragma unroll
    for (int ib = 0; ib < NB; ib++) {
        const int b = b0 + ib * 128;
        out[(size_t)b * T_ + t] = acc[ib];
    }
}

// ============================================================================
extern "C" void kernel_launch(void* const* d_in, const int* in_sizes, int n_in,
                              void* d_out, int out_size)
{
    const float* x       = (const float*)d_in[0];  // [B, T, D]
    const float* centers = (const float*)d_in[1];  // [T, K, D]
    const float* wlog    = (const float*)d_in[2];  // [T, K]
    const float* logvar  = (const float*)d_in[3];  // [T, K, D]
    const float* cov     = (const float*)d_in[4];  // [T, K, 28]

    const int B = in_sizes[0] / (T_ * D_);         // 2048

    dim3 grid(B / (128 * NB), T_);                 // (4, 512)
    pecd_fused_kernel<<<grid, 128>>>(x, centers, wlog, logvar, cov, (float*)d_out);
}